// round 3
// baseline (speedup 1.0000x reference)
#include <cuda_runtime.h>
#include <math.h>

#define NA 15000
#define NE 300000
#define FF 128
#define NRBF 20
#define NL 3
#define CUTOFF 5.0f
#define PI_F 3.14159265358979f

// ---------------- static scratch (no allocations allowed) ----------------
__device__ float4 g_dirf[NE];          // (dir.x, dir.y, dir.z, fcut)
__device__ float g_phis[NE * NRBF];    // phi * fcut
__device__ float g_x[NA * 384];
__device__ float g_h[NA * 128];
__device__ float g_ctx[NA * 256];
__device__ float g_mumix[NA * 3 * 256];
__device__ float g_muA[NA * 384];
__device__ float g_muB[NA * 384];
// CSR over idx_i
__device__ int g_cnt[NA];
__device__ int g_rowptr[NA + 1];
__device__ int g_head[NA];
__device__ int g_order[NE];

// ---------------- edge geometry: dirf, phi*fcut ----------------
__global__ void geom_kernel(const float* __restrict__ rij) {
    int e = blockIdx.x * blockDim.x + threadIdx.x;
    if (e >= NE) return;
    float r0 = rij[e * 3 + 0], r1 = rij[e * 3 + 1], r2 = rij[e * 3 + 2];
    float d = sqrtf(r0 * r0 + r1 * r1 + r2 * r2);
    float inv = 1.0f / d;
    float fc = (d < CUTOFF) ? 0.5f * (cosf(d * PI_F / CUTOFF) + 1.0f) : 0.0f;
    g_dirf[e] = make_float4(r0 * inv, r1 * inv, r2 * inv, fc);
    const float width = CUTOFF / (NRBF - 1);
    const float coeff = -0.5f / (width * width);
#pragma unroll
    for (int k = 0; k < NRBF; k++) {
        float t = d - width * k;
        g_phis[e * NRBF + k] = expf(coeff * t * t) * fc;
    }
}

// ---------------- init q, zero muA, zero CSR counters ----------------
__global__ void init_kernel(const int* __restrict__ z, const float* __restrict__ emb,
                            float* __restrict__ q) {
    int i = blockIdx.x * blockDim.x + threadIdx.x;
    if (i >= NA * 384) return;
    g_muA[i] = 0.0f;
    if (i < NA * FF) {
        int a = i >> 7, f = i & 127;
        q[i] = emb[z[a] * FF + f];
    }
    if (i < NA) g_cnt[i] = 0;
}

// ---------------- CSR build ----------------
__global__ void hist_kernel(const int* __restrict__ idx_i) {
    int e = blockIdx.x * blockDim.x + threadIdx.x;
    if (e < NE) atomicAdd(&g_cnt[idx_i[e]], 1);
}

#define SCAN_T 256
#define SCAN_CH ((NA + SCAN_T - 1) / SCAN_T)
__global__ void scan_kernel() {
    __shared__ int sh[SCAN_T];
    int t = threadIdx.x;
    int start = t * SCAN_CH;
    int s = 0;
    for (int k = 0; k < SCAN_CH; k++) {
        int i = start + k;
        if (i < NA) s += g_cnt[i];
    }
    sh[t] = s;
    __syncthreads();
    for (int off = 1; off < SCAN_T; off <<= 1) {
        int v = (t >= off) ? sh[t - off] : 0;
        __syncthreads();
        sh[t] += v;
        __syncthreads();
    }
    int base = (t == 0) ? 0 : sh[t - 1];
    for (int k = 0; k < SCAN_CH; k++) {
        int i = start + k;
        if (i < NA) {
            g_rowptr[i] = base;
            g_head[i] = base;
            base += g_cnt[i];
        }
    }
    if (t == SCAN_T - 1) g_rowptr[NA] = base;
}

__global__ void scatter_kernel(const int* __restrict__ idx_i) {
    int e = blockIdx.x * blockDim.x + threadIdx.x;
    if (e >= NE) return;
    int pos = atomicAdd(&g_head[idx_i[e]], 1);
    g_order[pos] = e;
}

// ---------------- atomic-free edge kernel (CSR, per-atom ownership) ----------------
// Block handles several atoms (grid-stride); thread = one feature f.
// Per edge: filters from phi (regs-resident weights), gather x[j], mu_in[j],
// accumulate dq/dmu in registers; write q[i] += dq, mu_out[i] = mu_in[i] + dmu.
__global__ void __launch_bounds__(128) edge_kernel(const float* __restrict__ W,
                                                   const float* __restrict__ b,
                                                   int layer,
                                                   const int* __restrict__ idx_j,
                                                   const float* __restrict__ mu_in,
                                                   float* __restrict__ mu_out,
                                                   float* __restrict__ q) {
    int f = threadIdx.x;
    float w0[NRBF], w1[NRBF], w2[NRBF];
#pragma unroll
    for (int k = 0; k < NRBF; k++) {
        const float* row = W + k * (NL * 384) + layer * 384;
        w0[k] = row[f];
        w1[k] = row[128 + f];
        w2[k] = row[256 + f];
    }
    float b0 = b[layer * 384 + f];
    float b1v = b[layer * 384 + 128 + f];
    float b2v = b[layer * 384 + 256 + f];

    for (int a = blockIdx.x; a < NA; a += gridDim.x) {
        int s = g_rowptr[a], eend = g_rowptr[a + 1];
        float accq = 0.f, acc0 = 0.f, acc1 = 0.f, acc2 = 0.f;
        for (int t = s; t < eend; t++) {
            int e = g_order[t];
            const float4* p4 = (const float4*)(g_phis + e * NRBF);
            float4 P0 = p4[0], P1 = p4[1], P2 = p4[2], P3 = p4[3], P4 = p4[4];
            float ph[NRBF] = {P0.x, P0.y, P0.z, P0.w, P1.x, P1.y, P1.z, P1.w,
                              P2.x, P2.y, P2.z, P2.w, P3.x, P3.y, P3.z, P3.w,
                              P4.x, P4.y, P4.z, P4.w};
            float4 df = g_dirf[e];
            float a0 = b0 * df.w, a1 = b1v * df.w, a2 = b2v * df.w;
#pragma unroll
            for (int k = 0; k < NRBF; k++) {
                a0 += ph[k] * w0[k];
                a1 += ph[k] * w1[k];
                a2 += ph[k] * w2[k];
            }
            int j = __ldg(idx_j + e);
            const float* xj = g_x + j * 384;
            float dq   = a0 * __ldg(xj + f);
            float dmuR = a1 * __ldg(xj + 128 + f);
            float dmm  = a2 * __ldg(xj + 256 + f);
            const float* mj = mu_in + j * 384;
            accq += dq;
            acc0 += dmuR * df.x + dmm * __ldg(mj + f);
            acc1 += dmuR * df.y + dmm * __ldg(mj + 128 + f);
            acc2 += dmuR * df.z + dmm * __ldg(mj + 256 + f);
        }
        q[a * 128 + f] += accq;
        mu_out[a * 384 + f]       = mu_in[a * 384 + f] + acc0;
        mu_out[a * 384 + 128 + f] = mu_in[a * 384 + 128 + f] + acc1;
        mu_out[a * 384 + 256 + f] = mu_in[a * 384 + 256 + f] + acc2;
    }
}

// ---------------- SGEMM: C = act(A@B + bias), 128x128 tile, 8x8/thread ----------------
// A: (M,K) row-major, B: (K,N) row-major, bias: (N). N % 128 == 0, K % 8 == 0.
__global__ void __launch_bounds__(256) sgemm_kernel(const float* __restrict__ A,
                                                    const float* __restrict__ B,
                                                    const float* __restrict__ bias,
                                                    float* __restrict__ C,
                                                    int M, int N, int K, int act) {
    __shared__ float As[8][128];
    __shared__ float Bs[8][128];
    int tid = threadIdx.x;
    int row0 = blockIdx.y * 128, col0 = blockIdx.x * 128;
    int aRow = tid >> 1, aK = (tid & 1) << 2;
    int bK = tid >> 5, bN = (tid & 31) << 2;
    int tx = tid & 15, ty = tid >> 4;
    float acc[8][8];
#pragma unroll
    for (int i = 0; i < 8; i++)
#pragma unroll
        for (int j = 0; j < 8; j++) acc[i][j] = 0.f;

    bool aval = (row0 + aRow) < M;
    const float* Aptr = A + (size_t)(row0 + aRow) * K + aK;

    for (int k0 = 0; k0 < K; k0 += 8) {
        float4 av = aval ? *(const float4*)(Aptr + k0) : make_float4(0.f, 0.f, 0.f, 0.f);
        As[aK + 0][aRow] = av.x;
        As[aK + 1][aRow] = av.y;
        As[aK + 2][aRow] = av.z;
        As[aK + 3][aRow] = av.w;
        *(float4*)&Bs[bK][bN] = *(const float4*)(B + (size_t)(k0 + bK) * N + col0 + bN);
        __syncthreads();
#pragma unroll
        for (int kk = 0; kk < 8; kk++) {
            float4 A0 = *(const float4*)&As[kk][ty * 8];
            float4 A1 = *(const float4*)&As[kk][ty * 8 + 4];
            float4 B0 = *(const float4*)&Bs[kk][tx * 8];
            float4 B1 = *(const float4*)&Bs[kk][tx * 8 + 4];
            float aa[8] = {A0.x, A0.y, A0.z, A0.w, A1.x, A1.y, A1.z, A1.w};
            float bb[8] = {B0.x, B0.y, B0.z, B0.w, B1.x, B1.y, B1.z, B1.w};
#pragma unroll
            for (int i = 0; i < 8; i++)
#pragma unroll
                for (int j = 0; j < 8; j++) acc[i][j] += aa[i] * bb[j];
        }
        __syncthreads();
    }
    float bias8[8];
#pragma unroll
    for (int j = 0; j < 8; j++) bias8[j] = bias[col0 + tx * 8 + j];
#pragma unroll
    for (int i = 0; i < 8; i++) {
        int r = row0 + ty * 8 + i;
        if (r < M) {
            float out[8];
#pragma unroll
            for (int j = 0; j < 8; j++) {
                float v = acc[i][j] + bias8[j];
                if (act) v = v / (1.0f + expf(-v));
                out[j] = v;
            }
            *(float4*)(C + (size_t)r * N + col0 + tx * 8) = *(float4*)&out[0];
            *(float4*)(C + (size_t)r * N + col0 + tx * 8 + 4) = *(float4*)&out[4];
        }
    }
}

// ---------------- ctx = [q, ||mu_V||] ----------------
__global__ void ctx_kernel(const float* __restrict__ q) {
    int i = blockIdx.x * blockDim.x + threadIdx.x;
    if (i >= NA * FF) return;
    int a = i >> 7, f = i & 127;
    float v0 = g_mumix[(a * 3 + 0) * 256 + f];
    float v1 = g_mumix[(a * 3 + 1) * 256 + f];
    float v2 = g_mumix[(a * 3 + 2) * 256 + f];
    g_ctx[a * 256 + f] = q[i];
    g_ctx[a * 256 + 128 + f] = sqrtf(v0 * v0 + v1 * v1 + v2 * v2);
}

// ---------------- intra update of q and mu ----------------
__global__ void update_kernel(float* __restrict__ q, float* __restrict__ mu) {
    int i = blockIdx.x * blockDim.x + threadIdx.x;
    if (i >= NA * FF) return;
    int a = i >> 7, f = i & 127;
    float s = 0.0f;
    float xmu = g_x[a * 384 + 128 + f];
#pragma unroll
    for (int d = 0; d < 3; d++) {
        float mv = g_mumix[(a * 3 + d) * 256 + f];
        float mw = g_mumix[(a * 3 + d) * 256 + 128 + f];
        s += mv * mw;
        mu[(a * 3 + d) * 128 + f] += xmu * mw;
    }
    q[i] += g_x[a * 384 + f] + g_x[a * 384 + 256 + f] * s;
}

// ---------------- launcher ----------------
extern "C" void kernel_launch(void* const* d_in, const int* in_sizes, int n_in,
                              void* d_out, int out_size) {
    const float* r_ij      = (const float*)d_in[0];
    const float* embedding = (const float*)d_in[1];
    const float* filt_W    = (const float*)d_in[2];
    const float* filt_b    = (const float*)d_in[3];
    const float* inter_W1  = (const float*)d_in[4];
    const float* inter_b1  = (const float*)d_in[5];
    const float* inter_W2  = (const float*)d_in[6];
    const float* inter_b2  = (const float*)d_in[7];
    const float* mix_W     = (const float*)d_in[8];
    const float* mix_b     = (const float*)d_in[9];
    const float* intra_W1  = (const float*)d_in[10];
    const float* intra_b1  = (const float*)d_in[11];
    const float* intra_W2  = (const float*)d_in[12];
    const float* intra_b2  = (const float*)d_in[13];
    const int*   z         = (const int*)d_in[14];
    const int*   idx_i     = (const int*)d_in[15];
    const int*   idx_j     = (const int*)d_in[16];

    float* q      = (float*)d_out;
    float* mu_fin = q + (size_t)NA * FF;

    void *p_h, *p_x, *p_ctx, *p_mumix, *p_muA, *p_muB;
    cudaGetSymbolAddress(&p_h, g_h);
    cudaGetSymbolAddress(&p_x, g_x);
    cudaGetSymbolAddress(&p_ctx, g_ctx);
    cudaGetSymbolAddress(&p_mumix, g_mumix);
    cudaGetSymbolAddress(&p_muA, g_muA);
    cudaGetSymbolAddress(&p_muB, g_muB);
    float* hbuf  = (float*)p_h;
    float* xbuf  = (float*)p_x;
    float* ctx   = (float*)p_ctx;
    float* mumix = (float*)p_mumix;
    float* muA   = (float*)p_muA;
    float* muB   = (float*)p_muB;

    geom_kernel<<<(NE + 255) / 256, 256>>>(r_ij);
    init_kernel<<<(NA * 384 + 255) / 256, 256>>>(z, embedding, q);
    hist_kernel<<<(NE + 255) / 256, 256>>>(idx_i);
    scan_kernel<<<1, SCAN_T>>>();
    scatter_kernel<<<(NE + 255) / 256, 256>>>(idx_i);

    // mu buffer schedule: L0: A(zero)->B, L1: B->A, L2: A->d_out
    float* mu_in_l[NL]  = {muA, muB, muA};
    float* mu_out_l[NL] = {muB, muA, mu_fin};

    for (int l = 0; l < NL; l++) {
        float* mi = mu_in_l[l];
        float* mo = mu_out_l[l];
        // h = silu(q @ W1 + b1)
        sgemm_kernel<<<dim3(1, (NA + 127) / 128), 256>>>(
            q, inter_W1 + (size_t)l * 128 * 128, inter_b1 + l * 128, hbuf, NA, 128, 128, 1);
        // x = h @ W2 + b2
        sgemm_kernel<<<dim3(3, (NA + 127) / 128), 256>>>(
            hbuf, inter_W2 + (size_t)l * 128 * 384, inter_b2 + l * 384, xbuf, NA, 384, 128, 0);
        // fused filters + edge messages (atomic-free, CSR)
        edge_kernel<<<1875, 128>>>(filt_W, filt_b, l, idx_j, mi, mo, q);
        // mu_mix = mu @ mix_W + mix_b   (45000 x 256)
        sgemm_kernel<<<dim3(2, (NA * 3 + 127) / 128), 256>>>(
            mo, mix_W + (size_t)l * 128 * 256, mix_b + l * 256, mumix, NA * 3, 256, 128, 0);
        // ctx = [q, ||mu_V||]
        ctx_kernel<<<(NA * FF + 255) / 256, 256>>>(q);
        // h = silu(ctx @ intra_W1 + b1)
        sgemm_kernel<<<dim3(1, (NA + 127) / 128), 256>>>(
            ctx, intra_W1 + (size_t)l * 256 * 128, intra_b1 + l * 128, hbuf, NA, 128, 256, 1);
        // x = h @ intra_W2 + b2
        sgemm_kernel<<<dim3(3, (NA + 127) / 128), 256>>>(
            hbuf, intra_W2 + (size_t)l * 128 * 384, intra_b2 + l * 384, xbuf, NA, 384, 128, 0);
        // q += dq_intra + dqmu_intra ; mu += dmu_intra
        update_kernel<<<(NA * FF + 255) / 256, 256>>>(q, mo);
    }
}